// round 9
// baseline (speedup 1.0000x reference)
#include <cuda_runtime.h>
#include <stdint.h>
#include <math.h>

#define NB 4
#define LD 4096
#define LE 4096
#define DM 512
#define NH 8
#define DH 64
#define NU 45
#define NTOP 45

// ---------------- scratch (static __device__, no allocation) ----------------
__device__ float g_Q[NB * LD * DM];
__device__ float g_K[NB * LE * DM];
__device__ float g_V[NB * LE * DM];
__device__ float g_M[NB * NH * LD];
__device__ int   g_top[NB * NH * NTOP];
__device__ float g_se[NB * NH * NTOP];            // row sums of P (atomic)
__device__ float g_upd[NB * NH * NTOP * DH];      // unnormalized P@V (atomic)
__device__ float g_vmean[NB * DM];
__device__ float g_base[NB * DM];

// ---------------- zero scratch that is atomically accumulated ----------------
__global__ void zero_kernel() {
    int i = blockIdx.x * 256 + threadIdx.x;
    if (i < NB * DM) g_vmean[i] = 0.0f;
    if (i < NB * NH * NTOP * DH) g_upd[i] = 0.0f;
    if (i < NB * NH * NTOP) g_se[i] = 0.0f;
}

// ---------------- helpers for tf32 tensor-core GEMM -------------------------
__device__ __forceinline__ uint32_t f2tf32(float v) {
    uint32_t u;
    asm volatile("cvt.rna.tf32.f32 %0, %1;" : "=r"(u) : "f"(v));
    return u;
}

__device__ __forceinline__ void cpasync16(void* smem_dst, const void* gsrc) {
    uint32_t d = (uint32_t)__cvta_generic_to_shared(smem_dst);
    asm volatile("cp.async.cg.shared.global [%0], [%1], 16;" :: "r"(d), "l"(gsrc));
}

#define CP_COMMIT() asm volatile("cp.async.commit_group;")
#define CP_WAIT(N)  asm volatile("cp.async.wait_group %0;" :: "n"(N))

#define AS_STRIDE 36
#define BS_STRIDE 136
#define AS_BUF (128 * AS_STRIDE)
#define BS_BUF (32 * BS_STRIDE)
#define TG_SMEM_BYTES ((2 * AS_BUF + 2 * BS_BUF) * 4)

// ---------------- tf32 tensor-core GEMM: C(Mx512)=A(Mx512)@W(512x512)+b -----
// Tiles converted to tf32 in smem ONCE per kt; MMA loop is pure LDS+MMA.
__global__ __launch_bounds__(256) void tgemm512(const float* __restrict__ A,
                                                const float* __restrict__ W,
                                                const float* __restrict__ bias,
                                                float* __restrict__ C) {
    extern __shared__ float sm[];
    float* As = sm;
    float* Bs = sm + 2 * AS_BUF;

    const int bm = blockIdx.y * 128;
    const int bn = blockIdx.x * 128;
    const int tid = threadIdx.x;
    const int lane = tid & 31;
    const int wid = tid >> 5;
    const int wm = (wid & 3) * 32;
    const int wn = (wid >> 2) * 64;
    const int g = lane >> 2;
    const int t4 = lane & 3;

    float acc[2][8][4];
#pragma unroll
    for (int mt = 0; mt < 2; mt++)
#pragma unroll
        for (int nt = 0; nt < 8; nt++)
#pragma unroll
            for (int c = 0; c < 4; c++) acc[mt][nt][c] = 0.0f;

    const float* Abase = A + (size_t)bm * DM;
    const float* Bbase = W + bn;

#define LOAD_TILE(kt, buf)                                                     \
    do {                                                                       \
        const float* Ag = Abase + (kt) * 32;                                   \
        const float* Bg = Bbase + (size_t)((kt) * 32) * DM;                    \
        _Pragma("unroll")                                                      \
        for (int i = 0; i < 4; i++) {                                          \
            int idx = tid + i * 256;                                           \
            int r = idx >> 3, c = (idx & 7) * 4;                               \
            cpasync16(&As[(buf) * AS_BUF + r * AS_STRIDE + c],                 \
                      Ag + (size_t)r * DM + c);                                \
        }                                                                      \
        _Pragma("unroll")                                                      \
        for (int i = 0; i < 4; i++) {                                          \
            int idx = tid + i * 256;                                           \
            int r = idx >> 5, c = (idx & 31) * 4;                              \
            cpasync16(&Bs[(buf) * BS_BUF + r * BS_STRIDE + c],                 \
                      Bg + (size_t)r * DM + c);                                \
        }                                                                      \
    } while (0)

    LOAD_TILE(0, 0);
    CP_COMMIT();

    for (int kt = 0; kt < 16; kt++) {
        const int buf = kt & 1;
        if (kt < 15) {
            LOAD_TILE(kt + 1, buf ^ 1);
            CP_COMMIT();
            CP_WAIT(1);
        } else {
            CP_WAIT(0);
        }
        __syncthreads();

        // ---- one-shot tf32 conversion of the freshly loaded tile ----
        {
            float* Ab = As + buf * AS_BUF;
            float* Bb = Bs + buf * BS_BUF;
#pragma unroll
            for (int i = 0; i < 4; i++) {
                int e = tid + i * 256;              // 1024 float4 in A tile
                int r = e >> 3, c4 = (e & 7) * 4;
                float4* pa = (float4*)&Ab[r * AS_STRIDE + c4];
                float4 va = *pa;
                uint4 ua = make_uint4(f2tf32(va.x), f2tf32(va.y),
                                      f2tf32(va.z), f2tf32(va.w));
                *(uint4*)pa = ua;
            }
#pragma unroll
            for (int i = 0; i < 4; i++) {
                int e = tid + i * 256;              // 1024 float4 in B tile
                int r = e >> 5, c4 = (e & 31) * 4;
                float4* pb = (float4*)&Bb[r * BS_STRIDE + c4];
                float4 vb = *pb;
                uint4 ub = make_uint4(f2tf32(vb.x), f2tf32(vb.y),
                                      f2tf32(vb.z), f2tf32(vb.w));
                *(uint4*)pb = ub;
            }
        }
        __syncthreads();

        const uint32_t* Au = (const uint32_t*)(As + buf * AS_BUF);
        const uint32_t* Bu = (const uint32_t*)(Bs + buf * BS_BUF);
#pragma unroll
        for (int k8 = 0; k8 < 4; k8++) {
            const int kk = k8 * 8;
            uint32_t af[2][4];
#pragma unroll
            for (int mt = 0; mt < 2; mt++) {
                const int rb = wm + mt * 16 + g;
                af[mt][0] = Au[(rb)*AS_STRIDE + kk + t4];
                af[mt][1] = Au[(rb + 8) * AS_STRIDE + kk + t4];
                af[mt][2] = Au[(rb)*AS_STRIDE + kk + t4 + 4];
                af[mt][3] = Au[(rb + 8) * AS_STRIDE + kk + t4 + 4];
            }
            uint32_t bf[8][2];
#pragma unroll
            for (int nt = 0; nt < 8; nt++) {
                const int nb = wn + nt * 8 + g;
                bf[nt][0] = Bu[(kk + t4) * BS_STRIDE + nb];
                bf[nt][1] = Bu[(kk + t4 + 4) * BS_STRIDE + nb];
            }
#pragma unroll
            for (int mt = 0; mt < 2; mt++)
#pragma unroll
                for (int nt = 0; nt < 8; nt++) {
                    asm volatile(
                        "mma.sync.aligned.m16n8k8.row.col.f32.tf32.tf32.f32 "
                        "{%0,%1,%2,%3}, {%4,%5,%6,%7}, {%8,%9}, {%0,%1,%2,%3};"
                        : "+f"(acc[mt][nt][0]), "+f"(acc[mt][nt][1]),
                          "+f"(acc[mt][nt][2]), "+f"(acc[mt][nt][3])
                        : "r"(af[mt][0]), "r"(af[mt][1]), "r"(af[mt][2]),
                          "r"(af[mt][3]), "r"(bf[nt][0]), "r"(bf[nt][1]));
                }
        }
        __syncthreads();
    }

#pragma unroll
    for (int mt = 0; mt < 2; mt++) {
        const int r0 = bm + wm + mt * 16 + g;
        const int r1 = r0 + 8;
#pragma unroll
        for (int nt = 0; nt < 8; nt++) {
            const int col = bn + wn + nt * 8 + 2 * t4;
            float2 bv = *(const float2*)&bias[col];
            float2 o0 = make_float2(acc[mt][nt][0] + bv.x, acc[mt][nt][1] + bv.y);
            float2 o1 = make_float2(acc[mt][nt][2] + bv.x, acc[mt][nt][3] + bv.y);
            *(float2*)&C[(size_t)r0 * DM + col] = o0;
            *(float2*)&C[(size_t)r1 * DM + col] = o1;
        }
    }
}

// ---------------- V column mean --------------------------------------------
__global__ void vmean_kernel() {
    const int b = blockIdx.x >> 5;
    const int slab = blockIdx.x & 31;
    const int t = threadIdx.x;
    const float* base = g_V + ((size_t)b * LE + slab * 128) * DM + t;
    float s = 0.0f;
    for (int r = 0; r < 128; r++) s += base[(size_t)r * DM];
    atomicAdd(&g_vmean[b * DM + t], s * (1.0f / (float)LE));
}

// ---------------- ProbSparse measure M (per batch) --------------------------
__global__ __launch_bounds__(256) void sample_m_kernel(const int* __restrict__ sidx,
                                                       int b) {
    const int l = blockIdx.x;
    const int bl = b * LD + l;
    __shared__ float qs[DM];
    __shared__ int idx[NU];
    __shared__ float qk[NH][NU + 3];
    const int t = threadIdx.x;
    const int w = t >> 5;
    const int lane = t & 31;

    if (t < 128) ((float4*)qs)[t] = ((const float4*)(g_Q + (size_t)bl * DM))[t];
    if (t < NU) idx[t] = sidx[l * NU + t];
    __syncthreads();

    for (int u = w; u < NU; u += 8) {
        const float4* kp = (const float4*)(g_K + ((size_t)b * LE + idx[u]) * DM);
#pragma unroll
        for (int j = 0; j < 4; j++) {
            float4 kv = kp[j * 32 + lane];
            float4 qv = ((const float4*)qs)[j * 32 + lane];
            float s = kv.x * qv.x + kv.y * qv.y + kv.z * qv.z + kv.w * qv.w;
            s += __shfl_xor_sync(0xffffffffu, s, 1);
            s += __shfl_xor_sync(0xffffffffu, s, 2);
            s += __shfl_xor_sync(0xffffffffu, s, 4);
            s += __shfl_xor_sync(0xffffffffu, s, 8);
            if (lane == 0) qk[2 * j][u] = s;
            if (lane == 16) qk[2 * j + 1][u] = s;
        }
    }
    __syncthreads();

    if (t < NH) {
        float mx = -INFINITY, sm = 0.0f;
        for (int u = 0; u < NU; u++) {
            float v = qk[t][u];
            mx = fmaxf(mx, v);
            sm += v;
        }
        g_M[((size_t)(b * NH + t)) * LD + l] = mx - sm * (1.0f / (float)LE);
    }
}

// ---------------- top-k set (45 of 4096) per (b,h), radix-select ------------
__global__ __launch_bounds__(1024) void topk_kernel(int b) {
    const int bh = b * NH + blockIdx.x;
    __shared__ unsigned int keys[LD];
    __shared__ int hist[4096];
    __shared__ unsigned long long sbest[32];
    __shared__ int sh_thr, sh_above, sh_out, sh_cand, sh_sel;
    const int t = threadIdx.x;
    const int lane = t & 31, w = t >> 5;

    for (int i = t; i < 4096; i += 1024) hist[i] = 0;
    __syncthreads();
    for (int i = t; i < LD; i += 1024) {
        unsigned int u = __float_as_uint(g_M[(size_t)bh * LD + i]);
        unsigned int key = (u & 0x80000000u) ? ~u : (u | 0x80000000u);
        keys[i] = key;
        atomicAdd(&hist[key >> 20], 1);
    }
    __syncthreads();

    if (t == 0) {
        int acc = 0, bin = 4095;
        for (; bin >= 0; bin--) {
            int h = hist[bin];
            if (acc + h >= NTOP) break;
            acc += h;
        }
        sh_thr = bin;
        sh_above = acc;
        sh_out = 0;
        sh_cand = 0;
    }
    __syncthreads();
    const unsigned int thr = (unsigned int)sh_thr;
    int* cand = hist;

    for (int i = t; i < LD; i += 1024) {
        unsigned int bin = keys[i] >> 20;
        if (bin > thr) {
            int p = atomicAdd(&sh_out, 1);
            g_top[bh * NTOP + p] = i;
        } else if (bin == thr) {
            int c = atomicAdd(&sh_cand, 1);
            cand[c] = i;
        }
    }
    __syncthreads();

    const int need = NTOP - sh_above;
    const int cn = sh_cand;
    for (int it = 0; it < need; it++) {
        unsigned long long best = 0;
        for (int i = t; i < cn; i += 1024) {
            int idx = cand[i];
            if (idx >= 0) {
                unsigned long long sc =
                    ((unsigned long long)keys[idx] << 32) | (unsigned int)(~idx);
                if (sc > best) best = sc;
            }
        }
#pragma unroll
        for (int o = 16; o > 0; o >>= 1) {
            unsigned long long v = __shfl_xor_sync(0xffffffffu, best, o);
            if (v > best) best = v;
        }
        if (lane == 0) sbest[w] = best;
        __syncthreads();
        if (w == 0) {
            unsigned long long b2 = sbest[lane];
#pragma unroll
            for (int o = 16; o > 0; o >>= 1) {
                unsigned long long v = __shfl_xor_sync(0xffffffffu, b2, o);
                if (v > b2) b2 = v;
            }
            if (lane == 0) {
                int widx = (int)(~(unsigned int)(b2 & 0xffffffffu));
                g_top[bh * NTOP + sh_above + it] = widx;
                sh_sel = widx;
            }
        }
        __syncthreads();
        const int widx = sh_sel;
        for (int i = t; i < cn; i += 1024)
            if (cand[i] == widx) cand[i] = -1;
        __syncthreads();
    }
}

// ---------------- fused attention (per batch): P in smem, sum + P@V ---------
// grid (16, NH), 256 threads. kc chunk = 256 keys = 4 sub-chunks of 64.
__global__ __launch_bounds__(256) void fused_attn_kernel(int b) {
    const int kc = blockIdx.x;
    const int h = blockIdx.y;
    const int bh = b * NH + h;
    const int t = threadIdx.x;
    const int row = t >> 2;
    const int q4 = t & 3;

    __shared__ float qs[NU][DH];
    __shared__ float Vs[64][DH];
    __shared__ float Ps[NU][64];

    for (int p = t; p < NU * 16; p += 256) {
        const int u = p >> 4;
        const int i = p & 15;
        const int l = g_top[bh * NTOP + u];
        ((float4*)qs[u])[i] =
            ((const float4*)(g_Q + ((size_t)b * LD + l) * DM + h * DH))[i];
    }

    float acc[3][4];
    float sp[3];
#pragma unroll
    for (int it = 0; it < 3; it++) {
        sp[it] = 0.0f;
#pragma unroll
        for (int c = 0; c < 4; c++) acc[it][c] = 0.0f;
    }
    __syncthreads();

    for (int sc = 0; sc < 4; sc++) {
        const int kbase = kc * 256 + sc * 64;

        for (int p = t; p < 64 * 16; p += 256) {
            const int kk = p >> 4;
            const int i = p & 15;
            ((float4*)Vs[kk])[i] =
                ((const float4*)(g_V + ((size_t)b * LE + kbase + kk) * DM + h * DH))[i];
        }

        const float4* kp =
            (const float4*)(g_K + ((size_t)b * LE + kbase + row) * DM + h * DH) + q4 * 4;
        float4 kr0 = kp[0], kr1 = kp[1], kr2 = kp[2], kr3 = kp[3];

#pragma unroll 5
        for (int u = 0; u < NU; u++) {
            const float4* qq = (const float4*)(qs[u]) + q4 * 4;
            float4 q0 = qq[0], q1 = qq[1], q2 = qq[2], q3 = qq[3];
            float s = kr0.x * q0.x + kr0.y * q0.y + kr0.z * q0.z + kr0.w * q0.w
                    + kr1.x * q1.x + kr1.y * q1.y + kr1.z * q1.z + kr1.w * q1.w
                    + kr2.x * q2.x + kr2.y * q2.y + kr2.z * q2.z + kr2.w * q2.w
                    + kr3.x * q3.x + kr3.y * q3.y + kr3.z * q3.z + kr3.w * q3.w;
            s += __shfl_xor_sync(0xffffffffu, s, 1);
            s += __shfl_xor_sync(0xffffffffu, s, 2);
            if (q4 == 0) Ps[u][row] = __expf(s * 0.125f);
        }
        __syncthreads();

#pragma unroll
        for (int it = 0; it < 3; it++) {
            const int p = t + it * 256;
            if (p < NU * 16) {
                const int u = p >> 4;
                const int d4 = p & 15;
                float a0 = acc[it][0], a1 = acc[it][1], a2 = acc[it][2], a3 = acc[it][3];
                float ss = 0.0f;
                for (int kk = 0; kk < 64; kk++) {
                    const float pw = Ps[u][kk];
                    float4 vv = ((float4*)Vs[kk])[d4];
                    a0 += pw * vv.x; a1 += pw * vv.y;
                    a2 += pw * vv.z; a3 += pw * vv.w;
                    ss += pw;
                }
                acc[it][0] = a0; acc[it][1] = a1; acc[it][2] = a2; acc[it][3] = a3;
                if (d4 == 0) sp[it] += ss;
            }
        }
        __syncthreads();
    }

#pragma unroll
    for (int it = 0; it < 3; it++) {
        const int p = t + it * 256;
        if (p < NU * 16) {
            const int u = p >> 4;
            const int d4 = p & 15;
            float* dst = g_upd + ((size_t)(bh * NTOP + u)) * DH + d4 * 4;
            atomicAdd(dst + 0, acc[it][0]);
            atomicAdd(dst + 1, acc[it][1]);
            atomicAdd(dst + 2, acc[it][2]);
            atomicAdd(dst + 3, acc[it][3]);
            if (d4 == 0) atomicAdd(&g_se[bh * NTOP + u], sp[it]);
        }
    }
}

// ---------------- base output row per batch: vmean @ Wo + bo ----------------
__global__ void baseout_kernel(const float* __restrict__ Wo, const float* __restrict__ bo) {
    const int b = blockIdx.x;
    const int lane = threadIdx.x & 31;
    const int w = threadIdx.x >> 5;
    const int col = blockIdx.y * 32 + lane;
    float s = 0.0f;
    const int k0 = w * 64;
#pragma unroll 8
    for (int k = k0; k < k0 + 64; k++)
        s += g_vmean[b * DM + k] * Wo[(size_t)k * DM + col];
    __shared__ float red[8][32];
    red[w][lane] = s;
    __syncthreads();
    if (w == 0) {
        float tot = bo[col];
#pragma unroll
        for (int j = 0; j < 8; j++) tot += red[j][lane];
        g_base[b * DM + col] = tot;
    }
}

// ---------------- fill output with base rows --------------------------------
__global__ void fill_kernel(float* __restrict__ out) {
    const size_t bl = blockIdx.x;
    const int b = blockIdx.x >> 12;
    float4 v = ((const float4*)(g_base + b * DM))[threadIdx.x];
    ((float4*)(out + bl * DM))[threadIdx.x] = v;
}

// ---------------- scatter corrections: (upd/se - vmean_h) @ Wo_h ------------
__global__ void scatter_kernel(const float* __restrict__ Wo, float* __restrict__ out) {
    const int u = blockIdx.x;
    const int h = blockIdx.y;
    const int b = blockIdx.z;
    const int bh = b * NH + h;
    __shared__ float delta[DH];
    __shared__ int lsh;
    __shared__ float inv_sh;
    const int t = threadIdx.x;

    if (t == 0) {
        lsh = g_top[bh * NTOP + u];
        inv_sh = 1.0f / g_se[bh * NTOP + u];
    }
    __syncthreads();
    if (t < DH)
        delta[t] = g_upd[((size_t)(bh * NTOP + u)) * DH + t] * inv_sh
                 - g_vmean[b * DM + h * DH + t];
    __syncthreads();

    const int l = lsh;
    float s = 0.0f;
#pragma unroll 8
    for (int d = 0; d < DH; d++) s += delta[d] * Wo[(size_t)(h * DH + d) * DM + t];
    atomicAdd(&out[((size_t)b * LD + l) * DM + t], s);
}

// ---------------- launch ----------------------------------------------------
extern "C" void kernel_launch(void* const* d_in, const int* in_sizes, int n_in,
                              void* d_out, int out_size) {
    const float* x       = (const float*)d_in[0];
    const float* context = (const float*)d_in[1];
    const float* Wq      = (const float*)d_in[2];
    const float* bq      = (const float*)d_in[3];
    const float* Wk      = (const float*)d_in[4];
    const float* bk      = (const float*)d_in[5];
    const float* Wv      = (const float*)d_in[6];
    const float* bv      = (const float*)d_in[7];
    const float* Wo      = (const float*)d_in[8];
    const float* bo      = (const float*)d_in[9];
    const int*   sidx    = (const int*)d_in[10];
    float* out = (float*)d_out;

    float *pQ, *pK, *pV;
    cudaGetSymbolAddress((void**)&pQ, g_Q);
    cudaGetSymbolAddress((void**)&pK, g_K);
    cudaGetSymbolAddress((void**)&pV, g_V);

    static int inited = 0;
    static cudaStream_t s1, s2;
    static cudaEvent_t ev0, evQK[NB], evV[NB], evFill;
    if (!inited) {
        cudaFuncSetAttribute(tgemm512, cudaFuncAttributeMaxDynamicSharedMemorySize,
                             TG_SMEM_BYTES);
        cudaStreamCreateWithFlags(&s1, cudaStreamNonBlocking);
        cudaStreamCreateWithFlags(&s2, cudaStreamNonBlocking);
        cudaEventCreateWithFlags(&ev0, cudaEventDisableTiming);
        for (int b = 0; b < NB; b++) {
            cudaEventCreateWithFlags(&evQK[b], cudaEventDisableTiming);
            cudaEventCreateWithFlags(&evV[b], cudaEventDisableTiming);
        }
        cudaEventCreateWithFlags(&evFill, cudaEventDisableTiming);
        inited = 1;
    }

    const dim3 gg(DM / 128, LD / 128);   // per-batch GEMM: 128 blocks

    // main: zero first
    zero_kernel<<<360, 256>>>();
    cudaEventRecord(ev0, 0);

    // s1: per-batch Q,K GEMMs then per-batch V GEMMs
    cudaStreamWaitEvent(s1, ev0, 0);
    for (int b = 0; b < NB; b++) {
        tgemm512<<<gg, 256, TG_SMEM_BYTES, s1>>>(x + (size_t)b * LD * DM, Wq, bq,
                                                 pQ + (size_t)b * LD * DM);
        tgemm512<<<gg, 256, TG_SMEM_BYTES, s1>>>(context + (size_t)b * LE * DM, Wk, bk,
                                                 pK + (size_t)b * LE * DM);
        cudaEventRecord(evQK[b], s1);
    }
    for (int b = 0; b < NB; b++) {
        tgemm512<<<gg, 256, TG_SMEM_BYTES, s1>>>(context + (size_t)b * LE * DM, Wv, bv,
                                                 pV + (size_t)b * LE * DM);
        cudaEventRecord(evV[b], s1);
    }

    // s2: V-mean branch after all V done
    cudaStreamWaitEvent(s2, evV[NB - 1], 0);
    vmean_kernel<<<NB * 32, 512, 0, s2>>>();
    baseout_kernel<<<dim3(NB, 16), 256, 0, s2>>>(Wo, bo);
    fill_kernel<<<NB * LD, 128, 0, s2>>>(out);
    cudaEventRecord(evFill, s2);

    // main: per-batch sampling pipeline overlapping the GEMM stream
    for (int b = 0; b < NB; b++) {
        cudaStreamWaitEvent(0, evQK[b], 0);
        sample_m_kernel<<<LD, 256>>>(sidx, b);
        topk_kernel<<<NH, 1024>>>(b);
    }
    for (int b = 0; b < NB; b++) {
        cudaStreamWaitEvent(0, evV[b], 0);
        fused_attn_kernel<<<dim3(16, NH), 256>>>(b);
    }

    cudaStreamWaitEvent(0, evFill, 0);
    scatter_kernel<<<dim3(NTOP, NH, NB), 512>>>(Wo, out);
}

// round 12
// speedup vs baseline: 1.4077x; 1.4077x over previous
#include <cuda_runtime.h>
#include <stdint.h>
#include <math.h>

#define NB 4
#define LD 4096
#define LE 4096
#define DM 512
#define NH 8
#define DH 64
#define NU 45
#define NTOP 45

// ---------------- scratch (static __device__, no allocation) ----------------
__device__ float g_Q[NB * LD * DM];
__device__ float g_K[NB * LE * DM];
__device__ float g_V[NB * LE * DM];
__device__ float g_M[NB * NH * LD];
__device__ int   g_top[NB * NH * NTOP];
__device__ float g_se[NB * NH * NTOP];            // row sums of P (atomic)
__device__ float g_upd[NB * NH * NTOP * DH];      // unnormalized P@V (atomic)
__device__ float g_vmean[NB * DM];
__device__ float g_base[NB * DM];

// ---------------- zero scratch that is atomically accumulated ----------------
__global__ void zero_kernel() {
    int i = blockIdx.x * 256 + threadIdx.x;
    if (i < NB * DM) g_vmean[i] = 0.0f;
    if (i < NB * NH * NTOP * DH) g_upd[i] = 0.0f;
    if (i < NB * NH * NTOP) g_se[i] = 0.0f;
}

// ---------------- helpers for tf32 tensor-core GEMM -------------------------
__device__ __forceinline__ uint32_t f2tf32(float v) {
    uint32_t u;
    asm volatile("cvt.rna.tf32.f32 %0, %1;" : "=r"(u) : "f"(v));
    return u;
}

__device__ __forceinline__ void cpasync16(void* smem_dst, const void* gsrc) {
    uint32_t d = (uint32_t)__cvta_generic_to_shared(smem_dst);
    asm volatile("cp.async.cg.shared.global [%0], [%1], 16;" :: "r"(d), "l"(gsrc));
}

#define CP_COMMIT() asm volatile("cp.async.commit_group;")
#define CP_WAIT(N)  asm volatile("cp.async.wait_group %0;" :: "n"(N))

#define AS_STRIDE 36
#define BS_STRIDE 136
#define AS_BUF (128 * AS_STRIDE)
#define BS_BUF (32 * BS_STRIDE)
#define TG_SMEM_BYTES ((2 * AS_BUF + 2 * BS_BUF) * 4)

// ---------------- tf32 tensor-core GEMM: C(Mx512)=A(Mx512)@W(512x512)+b -----
__global__ __launch_bounds__(256) void tgemm512(const float* __restrict__ A,
                                                const float* __restrict__ W,
                                                const float* __restrict__ bias,
                                                float* __restrict__ C) {
    extern __shared__ float sm[];
    float* As = sm;
    float* Bs = sm + 2 * AS_BUF;

    const int bm = blockIdx.y * 128;
    const int bn = blockIdx.x * 128;
    const int tid = threadIdx.x;
    const int lane = tid & 31;
    const int wid = tid >> 5;
    const int wm = (wid & 3) * 32;
    const int wn = (wid >> 2) * 64;
    const int g = lane >> 2;
    const int t4 = lane & 3;

    float acc[2][8][4];
#pragma unroll
    for (int mt = 0; mt < 2; mt++)
#pragma unroll
        for (int nt = 0; nt < 8; nt++)
#pragma unroll
            for (int c = 0; c < 4; c++) acc[mt][nt][c] = 0.0f;

    const float* Abase = A + (size_t)bm * DM;
    const float* Bbase = W + bn;

#define LOAD_TILE(kt, buf)                                                     \
    do {                                                                       \
        const float* Ag = Abase + (kt) * 32;                                   \
        const float* Bg = Bbase + (size_t)((kt) * 32) * DM;                    \
        _Pragma("unroll")                                                      \
        for (int i = 0; i < 4; i++) {                                          \
            int idx = tid + i * 256;                                           \
            int r = idx >> 3, c = (idx & 7) * 4;                               \
            cpasync16(&As[(buf) * AS_BUF + r * AS_STRIDE + c],                 \
                      Ag + (size_t)r * DM + c);                                \
        }                                                                      \
        _Pragma("unroll")                                                      \
        for (int i = 0; i < 4; i++) {                                          \
            int idx = tid + i * 256;                                           \
            int r = idx >> 5, c = (idx & 31) * 4;                              \
            cpasync16(&Bs[(buf) * BS_BUF + r * BS_STRIDE + c],                 \
                      Bg + (size_t)r * DM + c);                                \
        }                                                                      \
    } while (0)

    LOAD_TILE(0, 0);
    CP_COMMIT();

    for (int kt = 0; kt < 16; kt++) {
        const int buf = kt & 1;
        if (kt < 15) {
            LOAD_TILE(kt + 1, buf ^ 1);
            CP_COMMIT();
            CP_WAIT(1);
        } else {
            CP_WAIT(0);
        }
        __syncthreads();

        const float* Ab = As + buf * AS_BUF;
        const float* Bb = Bs + buf * BS_BUF;
#pragma unroll
        for (int k8 = 0; k8 < 4; k8++) {
            const int kk = k8 * 8;
            uint32_t af[2][4];
#pragma unroll
            for (int mt = 0; mt < 2; mt++) {
                const int rb = wm + mt * 16 + g;
                af[mt][0] = f2tf32(Ab[(rb)*AS_STRIDE + kk + t4]);
                af[mt][1] = f2tf32(Ab[(rb + 8) * AS_STRIDE + kk + t4]);
                af[mt][2] = f2tf32(Ab[(rb)*AS_STRIDE + kk + t4 + 4]);
                af[mt][3] = f2tf32(Ab[(rb + 8) * AS_STRIDE + kk + t4 + 4]);
            }
            uint32_t bf[8][2];
#pragma unroll
            for (int nt = 0; nt < 8; nt++) {
                const int nb = wn + nt * 8 + g;
                bf[nt][0] = f2tf32(Bb[(kk + t4) * BS_STRIDE + nb]);
                bf[nt][1] = f2tf32(Bb[(kk + t4 + 4) * BS_STRIDE + nb]);
            }
#pragma unroll
            for (int mt = 0; mt < 2; mt++)
#pragma unroll
                for (int nt = 0; nt < 8; nt++) {
                    asm volatile(
                        "mma.sync.aligned.m16n8k8.row.col.f32.tf32.tf32.f32 "
                        "{%0,%1,%2,%3}, {%4,%5,%6,%7}, {%8,%9}, {%0,%1,%2,%3};"
                        : "+f"(acc[mt][nt][0]), "+f"(acc[mt][nt][1]),
                          "+f"(acc[mt][nt][2]), "+f"(acc[mt][nt][3])
                        : "r"(af[mt][0]), "r"(af[mt][1]), "r"(af[mt][2]),
                          "r"(af[mt][3]), "r"(bf[nt][0]), "r"(bf[nt][1]));
                }
        }
        __syncthreads();
    }

#pragma unroll
    for (int mt = 0; mt < 2; mt++) {
        const int r0 = bm + wm + mt * 16 + g;
        const int r1 = r0 + 8;
#pragma unroll
        for (int nt = 0; nt < 8; nt++) {
            const int col = bn + wn + nt * 8 + 2 * t4;
            float2 bv = *(const float2*)&bias[col];
            float2 o0 = make_float2(acc[mt][nt][0] + bv.x, acc[mt][nt][1] + bv.y);
            float2 o1 = make_float2(acc[mt][nt][2] + bv.x, acc[mt][nt][3] + bv.y);
            *(float2*)&C[(size_t)r0 * DM + col] = o0;
            *(float2*)&C[(size_t)r1 * DM + col] = o1;
        }
    }
}

// ---------------- V column mean --------------------------------------------
__global__ void vmean_kernel() {
    const int b = blockIdx.x >> 5;
    const int slab = blockIdx.x & 31;
    const int t = threadIdx.x;
    const float* base = g_V + ((size_t)b * LE + slab * 128) * DM + t;
    float s = 0.0f;
    for (int r = 0; r < 128; r++) s += base[(size_t)r * DM];
    atomicAdd(&g_vmean[b * DM + t], s * (1.0f / (float)LE));
}

// ---------------- ProbSparse measure M: warp-cooperative coalesced gather ---
__global__ __launch_bounds__(256) void sample_m_kernel(const int* __restrict__ sidx) {
    const int bl = blockIdx.x;
    const int b = bl >> 12;
    const int l = bl & (LD - 1);
    __shared__ float qs[DM];
    __shared__ int idx[NU];
    __shared__ float qk[NH][NU + 3];
    const int t = threadIdx.x;
    const int w = t >> 5;
    const int lane = t & 31;

    if (t < 128) ((float4*)qs)[t] = ((const float4*)(g_Q + (size_t)bl * DM))[t];
    if (t < NU) idx[t] = sidx[l * NU + t];
    __syncthreads();

    for (int u = w; u < NU; u += 8) {
        const float4* kp = (const float4*)(g_K + ((size_t)b * LE + idx[u]) * DM);
#pragma unroll
        for (int j = 0; j < 4; j++) {
            float4 kv = kp[j * 32 + lane];
            float4 qv = ((const float4*)qs)[j * 32 + lane];
            float s = kv.x * qv.x + kv.y * qv.y + kv.z * qv.z + kv.w * qv.w;
            s += __shfl_xor_sync(0xffffffffu, s, 1);
            s += __shfl_xor_sync(0xffffffffu, s, 2);
            s += __shfl_xor_sync(0xffffffffu, s, 4);
            s += __shfl_xor_sync(0xffffffffu, s, 8);
            if (lane == 0) qk[2 * j][u] = s;
            if (lane == 16) qk[2 * j + 1][u] = s;
        }
    }
    __syncthreads();

    if (t < NH) {
        float mx = -INFINITY, sm = 0.0f;
        for (int u = 0; u < NU; u++) {
            float v = qk[t][u];
            mx = fmaxf(mx, v);
            sm += v;
        }
        g_M[((size_t)(b * NH + t)) * LD + l] = mx - sm * (1.0f / (float)LE);
    }
}

// ---------------- find largest bin T with suffix-count >= target ------------
// executed by warp 0 only (t < 32); cum/tot uniform across lanes
__device__ __forceinline__ void find_bin(const int* hist, int nbins, int target,
                                         int* sh_bin, int* sh_above, int lane) {
    int cum = 0;
    for (int base = nbins - 32; base >= 0; base -= 32) {
        int v = hist[base + lane];
        int tot = v;
#pragma unroll
        for (int o = 16; o > 0; o >>= 1) tot += __shfl_xor_sync(0xffffffffu, tot, o);
        if (cum + tot >= target) {
            if (lane == 0) {
                int c = cum;
                int b = base + 31;
                for (;; b--) {
                    int h = hist[b];
                    if (c + h >= target || b == base) break;
                    c += h;
                }
                *sh_bin = b;
                *sh_above = c;
            }
            return;
        }
        cum += tot;
    }
    if (lane == 0) { *sh_bin = 0; *sh_above = cum; }
}

// ---------------- exact top-k set via 3-pass radix select -------------------
// monotone key: flip for order; threshold refined over bits [31:20],[19:8],[7:0]
__global__ __launch_bounds__(1024) void topk_kernel() {
    const int bh = blockIdx.x;
    __shared__ unsigned int keys[LD];
    __shared__ int hist[4096];
    __shared__ int eqidx[512];
    __shared__ int sh_bin1, sh_above1, sh_bin2, sh_above2, sh_bin3, sh_above3;
    __shared__ int sh_out, sh_eqc;
    const int t = threadIdx.x;

    // load + monotone transform; clear hist
    for (int i = t; i < LD; i += 1024) {
        unsigned int u = __float_as_uint(g_M[(size_t)bh * LD + i]);
        keys[i] = (u & 0x80000000u) ? ~u : (u | 0x80000000u);
    }
    for (int i = t; i < 4096; i += 1024) hist[i] = 0;
    __syncthreads();

    // pass 1: bits [31:20]
    for (int i = t; i < LD; i += 1024) atomicAdd(&hist[keys[i] >> 20], 1);
    __syncthreads();
    if (t < 32) find_bin(hist, 4096, NTOP, &sh_bin1, &sh_above1, t);
    __syncthreads();
    const unsigned int b1 = (unsigned int)sh_bin1;
    const int above1 = sh_above1;
    __syncthreads();

    // pass 2: bits [19:8] within bin1
    for (int i = t; i < 4096; i += 1024) hist[i] = 0;
    __syncthreads();
    for (int i = t; i < LD; i += 1024)
        if ((keys[i] >> 20) == b1) atomicAdd(&hist[(keys[i] >> 8) & 0xFFFu], 1);
    __syncthreads();
    if (t < 32) find_bin(hist, 4096, NTOP - above1, &sh_bin2, &sh_above2, t);
    __syncthreads();
    const unsigned int b2 = (unsigned int)sh_bin2;
    const unsigned int pref2 = (b1 << 12) | b2;   // == keys[i] >> 8
    const int above12 = above1 + sh_above2;
    __syncthreads();

    // pass 3: bits [7:0] within (bin1, bin2)
    if (t < 256) hist[t] = 0;
    __syncthreads();
    for (int i = t; i < LD; i += 1024)
        if ((keys[i] >> 8) == pref2) atomicAdd(&hist[keys[i] & 0xFFu], 1);
    __syncthreads();
    if (t < 32) find_bin(hist, 256, NTOP - above12, &sh_bin3, &sh_above3, t);
    if (t == 0) { sh_out = 0; sh_eqc = 0; }
    __syncthreads();

    const unsigned int thr = (b1 << 20) | (b2 << 8) | (unsigned int)sh_bin3;

    // emit: strictly greater -> selected; equal -> tie list (min-index wins)
    for (int i = t; i < LD; i += 1024) {
        unsigned int k = keys[i];
        if (k > thr) {
            int p = atomicAdd(&sh_out, 1);
            g_top[bh * NTOP + p] = i;
        } else if (k == thr) {
            int c = atomicAdd(&sh_eqc, 1);
            if (c < 512) eqidx[c] = i;
        }
    }
    __syncthreads();

    if (t == 0) {
        const int a = sh_out;
        const int need = NTOP - a;
        int c = sh_eqc;
        if (c > 512) c = 512;
        for (int j = 0; j < need; j++) {
            int best = 1 << 30, bi = 0;
            for (int i2 = 0; i2 < c; i2++) {
                int v = eqidx[i2];
                if (v < best) { best = v; bi = i2; }
            }
            g_top[bh * NTOP + a + j] = best;
            eqidx[bi] = 1 << 30;
        }
    }
}

// ---------------- fused attention: P=exp(QK/8) in smem, sum + P@V ------------
__global__ __launch_bounds__(256) void fused_attn_kernel() {
    const int kc = blockIdx.x;
    const int h = blockIdx.y;
    const int b = blockIdx.z;
    const int bh = b * NH + h;
    const int t = threadIdx.x;
    const int row = t >> 2;
    const int q4 = t & 3;

    __shared__ float qs[NU][DH];
    __shared__ float Vs[64][DH];
    __shared__ float Ps[NU][64];

    for (int p = t; p < NU * 16; p += 256) {
        const int u = p >> 4;
        const int i = p & 15;
        const int l = g_top[bh * NTOP + u];
        ((float4*)qs[u])[i] =
            ((const float4*)(g_Q + ((size_t)b * LD + l) * DM + h * DH))[i];
    }

    float acc[3][4];
    float sp[3];
#pragma unroll
    for (int it = 0; it < 3; it++) {
        sp[it] = 0.0f;
#pragma unroll
        for (int c = 0; c < 4; c++) acc[it][c] = 0.0f;
    }
    __syncthreads();

    for (int sc = 0; sc < 8; sc++) {
        const int kbase = kc * 512 + sc * 64;

        for (int p = t; p < 64 * 16; p += 256) {
            const int kk = p >> 4;
            const int i = p & 15;
            ((float4*)Vs[kk])[i] =
                ((const float4*)(g_V + ((size_t)b * LE + kbase + kk) * DM + h * DH))[i];
        }

        const float4* kp =
            (const float4*)(g_K + ((size_t)b * LE + kbase + row) * DM + h * DH) + q4 * 4;
        float4 kr0 = kp[0], kr1 = kp[1], kr2 = kp[2], kr3 = kp[3];

#pragma unroll 5
        for (int u = 0; u < NU; u++) {
            const float4* qq = (const float4*)(qs[u]) + q4 * 4;
            float4 q0 = qq[0], q1 = qq[1], q2 = qq[2], q3 = qq[3];
            float s = kr0.x * q0.x + kr0.y * q0.y + kr0.z * q0.z + kr0.w * q0.w
                    + kr1.x * q1.x + kr1.y * q1.y + kr1.z * q1.z + kr1.w * q1.w
                    + kr2.x * q2.x + kr2.y * q2.y + kr2.z * q2.z + kr2.w * q2.w
                    + kr3.x * q3.x + kr3.y * q3.y + kr3.z * q3.z + kr3.w * q3.w;
            s += __shfl_xor_sync(0xffffffffu, s, 1);
            s += __shfl_xor_sync(0xffffffffu, s, 2);
            if (q4 == 0) Ps[u][row] = __expf(s * 0.125f);
        }
        __syncthreads();

#pragma unroll
        for (int it = 0; it < 3; it++) {
            const int p = t + it * 256;
            if (p < NU * 16) {
                const int u = p >> 4;
                const int d4 = p & 15;
                float a0 = acc[it][0], a1 = acc[it][1], a2 = acc[it][2], a3 = acc[it][3];
                float ss = 0.0f;
                for (int kk = 0; kk < 64; kk++) {
                    const float pw = Ps[u][kk];
                    float4 vv = ((float4*)Vs[kk])[d4];
                    a0 += pw * vv.x; a1 += pw * vv.y;
                    a2 += pw * vv.z; a3 += pw * vv.w;
                    ss += pw;
                }
                acc[it][0] = a0; acc[it][1] = a1; acc[it][2] = a2; acc[it][3] = a3;
                if (d4 == 0) sp[it] += ss;
            }
        }
        __syncthreads();
    }

#pragma unroll
    for (int it = 0; it < 3; it++) {
        const int p = t + it * 256;
        if (p < NU * 16) {
            const int u = p >> 4;
            const int d4 = p & 15;
            float* dst = g_upd + ((size_t)(bh * NTOP + u)) * DH + d4 * 4;
            atomicAdd(dst + 0, acc[it][0]);
            atomicAdd(dst + 1, acc[it][1]);
            atomicAdd(dst + 2, acc[it][2]);
            atomicAdd(dst + 3, acc[it][3]);
            if (d4 == 0) atomicAdd(&g_se[bh * NTOP + u], sp[it]);
        }
    }
}

// ---------------- base output row per batch: vmean @ Wo + bo ----------------
__global__ void baseout_kernel(const float* __restrict__ Wo, const float* __restrict__ bo) {
    const int b = blockIdx.x;
    const int lane = threadIdx.x & 31;
    const int w = threadIdx.x >> 5;
    const int col = blockIdx.y * 32 + lane;
    float s = 0.0f;
    const int k0 = w * 64;
#pragma unroll 8
    for (int k = k0; k < k0 + 64; k++)
        s += g_vmean[b * DM + k] * Wo[(size_t)k * DM + col];
    __shared__ float red[8][32];
    red[w][lane] = s;
    __syncthreads();
    if (w == 0) {
        float tot = bo[col];
#pragma unroll
        for (int j = 0; j < 8; j++) tot += red[j][lane];
        g_base[b * DM + col] = tot;
    }
}

// ---------------- fill output with base rows --------------------------------
__global__ void fill_kernel(float* __restrict__ out) {
    const size_t bl = blockIdx.x;
    const int b = blockIdx.x >> 12;
    float4 v = ((const float4*)(g_base + b * DM))[threadIdx.x];
    ((float4*)(out + bl * DM))[threadIdx.x] = v;
}

// ---------------- scatter corrections: (upd/se - vmean_h) @ Wo_h ------------
__global__ void scatter_kernel(const float* __restrict__ Wo, float* __restrict__ out) {
    const int u = blockIdx.x;
    const int h = blockIdx.y;
    const int b = blockIdx.z;
    const int bh = b * NH + h;
    __shared__ float delta[DH];
    __shared__ int lsh;
    __shared__ float inv_sh;
    const int t = threadIdx.x;

    if (t == 0) {
        lsh = g_top[bh * NTOP + u];
        inv_sh = 1.0f / g_se[bh * NTOP + u];
    }
    __syncthreads();
    if (t < DH)
        delta[t] = g_upd[((size_t)(bh * NTOP + u)) * DH + t] * inv_sh
                 - g_vmean[b * DM + h * DH + t];
    __syncthreads();

    const int l = lsh;
    float s = 0.0f;
#pragma unroll 8
    for (int d = 0; d < DH; d++) s += delta[d] * Wo[(size_t)(h * DH + d) * DM + t];
    atomicAdd(&out[((size_t)b * LD + l) * DM + t], s);
}

// ---------------- launch ----------------------------------------------------
extern "C" void kernel_launch(void* const* d_in, const int* in_sizes, int n_in,
                              void* d_out, int out_size) {
    const float* x       = (const float*)d_in[0];
    const float* context = (const float*)d_in[1];
    const float* Wq      = (const float*)d_in[2];
    const float* bq      = (const float*)d_in[3];
    const float* Wk      = (const float*)d_in[4];
    const float* bk      = (const float*)d_in[5];
    const float* Wv      = (const float*)d_in[6];
    const float* bv      = (const float*)d_in[7];
    const float* Wo      = (const float*)d_in[8];
    const float* bo      = (const float*)d_in[9];
    const int*   sidx    = (const int*)d_in[10];
    float* out = (float*)d_out;

    float *pQ, *pK, *pV;
    cudaGetSymbolAddress((void**)&pQ, g_Q);
    cudaGetSymbolAddress((void**)&pK, g_K);
    cudaGetSymbolAddress((void**)&pV, g_V);

    static int inited = 0;
    static cudaStream_t s1, s2;
    static cudaEvent_t ev0, evQ, evK, evV, evFill;
    if (!inited) {
        cudaFuncSetAttribute(tgemm512, cudaFuncAttributeMaxDynamicSharedMemorySize,
                             TG_SMEM_BYTES);
        cudaStreamCreateWithFlags(&s1, cudaStreamNonBlocking);
        cudaStreamCreateWithFlags(&s2, cudaStreamNonBlocking);
        cudaEventCreateWithFlags(&ev0, cudaEventDisableTiming);
        cudaEventCreateWithFlags(&evQ, cudaEventDisableTiming);
        cudaEventCreateWithFlags(&evK, cudaEventDisableTiming);
        cudaEventCreateWithFlags(&evV, cudaEventDisableTiming);
        cudaEventCreateWithFlags(&evFill, cudaEventDisableTiming);
        inited = 1;
    }

    // main: zero first (fused/scatter accumulate atomically into zeroed bufs)
    zero_kernel<<<360, 256>>>();
    cudaEventRecord(ev0, 0);

    // s1: Q-GEMM concurrent with K-GEMM on main
    cudaStreamWaitEvent(s1, ev0, 0);
    tgemm512<<<dim3(DM / 128, (NB * LD) / 128), 256, TG_SMEM_BYTES, s1>>>(x, Wq, bq, pQ);
    cudaEventRecord(evQ, s1);

    // main: K-GEMM
    tgemm512<<<dim3(DM / 128, (NB * LE) / 128), 256, TG_SMEM_BYTES>>>(context, Wk, bk, pK);
    cudaEventRecord(evK, 0);

    // s2: V branch starts after K-GEMM (overlaps sample_m)
    cudaStreamWaitEvent(s2, evK, 0);
    tgemm512<<<dim3(DM / 128, (NB * LE) / 128), 256, TG_SMEM_BYTES, s2>>>(context, Wv, bv, pV);
    cudaEventRecord(evV, s2);
    vmean_kernel<<<NB * 32, 512, 0, s2>>>();
    baseout_kernel<<<dim3(NB, 16), 256, 0, s2>>>(Wo, bo);
    fill_kernel<<<NB * LD, 128, 0, s2>>>(out);
    cudaEventRecord(evFill, s2);

    // main: sampling path (needs Q and K)
    cudaStreamWaitEvent(0, evQ, 0);
    sample_m_kernel<<<NB * LD, 256>>>(sidx);
    topk_kernel<<<NB * NH, 1024>>>();

    cudaStreamWaitEvent(0, evV, 0);       // fused needs V
    fused_attn_kernel<<<dim3(8, NH, NB), 256>>>();

    cudaStreamWaitEvent(0, evFill, 0);    // scatter writes over filled output
    scatter_kernel<<<dim3(NTOP, NH, NB), 512>>>(Wo, out);
}

// round 13
// speedup vs baseline: 1.4225x; 1.0106x over previous
#include <cuda_runtime.h>
#include <stdint.h>
#include <math.h>

#define NB 4
#define LD 4096
#define LE 4096
#define DM 512
#define NH 8
#define DH 64
#define NU 45
#define NTOP 45

// ---------------- scratch (static __device__, no allocation) ----------------
__device__ float g_Q[NB * LD * DM];
__device__ float g_K[NB * LE * DM];
__device__ float g_V[NB * LE * DM];
__device__ float g_M[NB * NH * LD];
__device__ int   g_top[NB * NH * NTOP];
__device__ float g_se[NB * NH * NTOP];            // row sums of P (atomic)
__device__ float g_upd[NB * NH * NTOP * DH];      // unnormalized P@V (atomic)
__device__ float g_vmean[NB * DM];
__device__ float g_base[NB * DM];

// ---------------- zero scratch that is atomically accumulated ----------------
__global__ void zero_kernel() {
    int i = blockIdx.x * 256 + threadIdx.x;
    if (i < NB * DM) g_vmean[i] = 0.0f;
    if (i < NB * NH * NTOP * DH) g_upd[i] = 0.0f;
    if (i < NB * NH * NTOP) g_se[i] = 0.0f;
}

// ---------------- helpers for tf32 tensor-core GEMM -------------------------
__device__ __forceinline__ uint32_t f2tf32(float v) {
    uint32_t u;
    asm volatile("cvt.rna.tf32.f32 %0, %1;" : "=r"(u) : "f"(v));
    return u;
}

__device__ __forceinline__ void cpasync16(void* smem_dst, const void* gsrc) {
    uint32_t d = (uint32_t)__cvta_generic_to_shared(smem_dst);
    asm volatile("cp.async.cg.shared.global [%0], [%1], 16;" :: "r"(d), "l"(gsrc));
}

#define CP_COMMIT() asm volatile("cp.async.commit_group;")
#define CP_WAIT(N)  asm volatile("cp.async.wait_group %0;" :: "n"(N))

#define AS_STRIDE 36
#define BS_STRIDE 136
#define AS_BUF (128 * AS_STRIDE)
#define BS_BUF (32 * BS_STRIDE)
#define TG_SMEM_BYTES ((2 * AS_BUF + 2 * BS_BUF) * 4)

// ---------------- tf32 tensor-core GEMM: C(Mx512)=A(Mx512)@W(512x512)+b -----
// block 128x128, BK=32, 128 threads = 4 warps (2x2), warp tile 64x64
// (mt=4, nt=8): fragment-LDS/MMA ratio 1.0 vs 1.5 of the old 32x64 tiling.
__global__ __launch_bounds__(128, 2) void tgemm512(const float* __restrict__ A,
                                                   const float* __restrict__ W,
                                                   const float* __restrict__ bias,
                                                   float* __restrict__ C) {
    extern __shared__ float sm[];
    float* As = sm;
    float* Bs = sm + 2 * AS_BUF;

    const int bm = blockIdx.y * 128;
    const int bn = blockIdx.x * 128;
    const int tid = threadIdx.x;
    const int lane = tid & 31;
    const int wid = tid >> 5;
    const int wm = (wid & 1) * 64;     // warp row offset in block
    const int wn = (wid >> 1) * 64;    // warp col offset in block
    const int g = lane >> 2;           // 0..7
    const int t4 = lane & 3;           // 0..3

    float acc[4][8][4];
#pragma unroll
    for (int mt = 0; mt < 4; mt++)
#pragma unroll
        for (int nt = 0; nt < 8; nt++)
#pragma unroll
            for (int c = 0; c < 4; c++) acc[mt][nt][c] = 0.0f;

    const float* Abase = A + (size_t)bm * DM;
    const float* Bbase = W + bn;

#define LOAD_TILE(kt, buf)                                                     \
    do {                                                                       \
        const float* Ag = Abase + (kt) * 32;                                   \
        const float* Bg = Bbase + (size_t)((kt) * 32) * DM;                    \
        _Pragma("unroll")                                                      \
        for (int i = 0; i < 8; i++) {                                          \
            int idx = tid + i * 128;                                           \
            int r = idx >> 3, c = (idx & 7) * 4;                               \
            cpasync16(&As[(buf) * AS_BUF + r * AS_STRIDE + c],                 \
                      Ag + (size_t)r * DM + c);                                \
        }                                                                      \
        _Pragma("unroll")                                                      \
        for (int i = 0; i < 8; i++) {                                          \
            int idx = tid + i * 128;                                           \
            int r = idx >> 5, c = (idx & 31) * 4;                              \
            cpasync16(&Bs[(buf) * BS_BUF + r * BS_STRIDE + c],                 \
                      Bg + (size_t)r * DM + c);                                \
        }                                                                      \
    } while (0)

    LOAD_TILE(0, 0);
    CP_COMMIT();

    for (int kt = 0; kt < 16; kt++) {
        const int buf = kt & 1;
        if (kt < 15) {
            LOAD_TILE(kt + 1, buf ^ 1);
            CP_COMMIT();
            CP_WAIT(1);
        } else {
            CP_WAIT(0);
        }
        __syncthreads();

        const float* Ab = As + buf * AS_BUF;
        const float* Bb = Bs + buf * BS_BUF;
#pragma unroll
        for (int k8 = 0; k8 < 4; k8++) {
            const int kk = k8 * 8;
            uint32_t af[4][4];
#pragma unroll
            for (int mt = 0; mt < 4; mt++) {
                const int rb = wm + mt * 16 + g;
                af[mt][0] = f2tf32(Ab[(rb)*AS_STRIDE + kk + t4]);
                af[mt][1] = f2tf32(Ab[(rb + 8) * AS_STRIDE + kk + t4]);
                af[mt][2] = f2tf32(Ab[(rb)*AS_STRIDE + kk + t4 + 4]);
                af[mt][3] = f2tf32(Ab[(rb + 8) * AS_STRIDE + kk + t4 + 4]);
            }
            uint32_t bf[8][2];
#pragma unroll
            for (int nt = 0; nt < 8; nt++) {
                const int nb = wn + nt * 8 + g;
                bf[nt][0] = f2tf32(Bb[(kk + t4) * BS_STRIDE + nb]);
                bf[nt][1] = f2tf32(Bb[(kk + t4 + 4) * BS_STRIDE + nb]);
            }
#pragma unroll
            for (int mt = 0; mt < 4; mt++)
#pragma unroll
                for (int nt = 0; nt < 8; nt++) {
                    asm volatile(
                        "mma.sync.aligned.m16n8k8.row.col.f32.tf32.tf32.f32 "
                        "{%0,%1,%2,%3}, {%4,%5,%6,%7}, {%8,%9}, {%0,%1,%2,%3};"
                        : "+f"(acc[mt][nt][0]), "+f"(acc[mt][nt][1]),
                          "+f"(acc[mt][nt][2]), "+f"(acc[mt][nt][3])
                        : "r"(af[mt][0]), "r"(af[mt][1]), "r"(af[mt][2]),
                          "r"(af[mt][3]), "r"(bf[nt][0]), "r"(bf[nt][1]));
                }
        }
        __syncthreads();
    }

    // ---- epilogue: bias add + store ----
#pragma unroll
    for (int mt = 0; mt < 4; mt++) {
        const int r0 = bm + wm + mt * 16 + g;
        const int r1 = r0 + 8;
#pragma unroll
        for (int nt = 0; nt < 8; nt++) {
            const int col = bn + wn + nt * 8 + 2 * t4;
            float2 bv = *(const float2*)&bias[col];
            float2 o0 = make_float2(acc[mt][nt][0] + bv.x, acc[mt][nt][1] + bv.y);
            float2 o1 = make_float2(acc[mt][nt][2] + bv.x, acc[mt][nt][3] + bv.y);
            *(float2*)&C[(size_t)r0 * DM + col] = o0;
            *(float2*)&C[(size_t)r1 * DM + col] = o1;
        }
    }
}

// ---------------- V column mean --------------------------------------------
__global__ void vmean_kernel() {
    const int b = blockIdx.x >> 5;
    const int slab = blockIdx.x & 31;
    const int t = threadIdx.x;
    const float* base = g_V + ((size_t)b * LE + slab * 128) * DM + t;
    float s = 0.0f;
    for (int r = 0; r < 128; r++) s += base[(size_t)r * DM];
    atomicAdd(&g_vmean[b * DM + t], s * (1.0f / (float)LE));
}

// ---------------- ProbSparse measure M: warp-cooperative coalesced gather ---
__global__ __launch_bounds__(256) void sample_m_kernel(const int* __restrict__ sidx) {
    const int bl = blockIdx.x;
    const int b = bl >> 12;
    const int l = bl & (LD - 1);
    __shared__ float qs[DM];
    __shared__ int idx[NU];
    __shared__ float qk[NH][NU + 3];
    const int t = threadIdx.x;
    const int w = t >> 5;
    const int lane = t & 31;

    if (t < 128) ((float4*)qs)[t] = ((const float4*)(g_Q + (size_t)bl * DM))[t];
    if (t < NU) idx[t] = sidx[l * NU + t];
    __syncthreads();

    for (int u = w; u < NU; u += 8) {
        const float4* kp = (const float4*)(g_K + ((size_t)b * LE + idx[u]) * DM);
#pragma unroll
        for (int j = 0; j < 4; j++) {
            float4 kv = kp[j * 32 + lane];
            float4 qv = ((const float4*)qs)[j * 32 + lane];
            float s = kv.x * qv.x + kv.y * qv.y + kv.z * qv.z + kv.w * qv.w;
            s += __shfl_xor_sync(0xffffffffu, s, 1);
            s += __shfl_xor_sync(0xffffffffu, s, 2);
            s += __shfl_xor_sync(0xffffffffu, s, 4);
            s += __shfl_xor_sync(0xffffffffu, s, 8);
            if (lane == 0) qk[2 * j][u] = s;
            if (lane == 16) qk[2 * j + 1][u] = s;
        }
    }
    __syncthreads();

    if (t < NH) {
        float mx = -INFINITY, sm = 0.0f;
        for (int u = 0; u < NU; u++) {
            float v = qk[t][u];
            mx = fmaxf(mx, v);
            sm += v;
        }
        g_M[((size_t)(b * NH + t)) * LD + l] = mx - sm * (1.0f / (float)LE);
    }
}

// ---------------- find largest bin T with suffix-count >= target ------------
__device__ __forceinline__ void find_bin(const int* hist, int nbins, int target,
                                         int* sh_bin, int* sh_above, int lane) {
    int cum = 0;
    for (int base = nbins - 32; base >= 0; base -= 32) {
        int v = hist[base + lane];
        int tot = v;
#pragma unroll
        for (int o = 16; o > 0; o >>= 1) tot += __shfl_xor_sync(0xffffffffu, tot, o);
        if (cum + tot >= target) {
            if (lane == 0) {
                int c = cum;
                int b = base + 31;
                for (;; b--) {
                    int h = hist[b];
                    if (c + h >= target || b == base) break;
                    c += h;
                }
                *sh_bin = b;
                *sh_above = c;
            }
            return;
        }
        cum += tot;
    }
    if (lane == 0) { *sh_bin = 0; *sh_above = cum; }
}

// ---------------- exact top-k set via 3-pass radix select -------------------
__global__ __launch_bounds__(1024) void topk_kernel() {
    const int bh = blockIdx.x;
    __shared__ unsigned int keys[LD];
    __shared__ int hist[4096];
    __shared__ int eqidx[512];
    __shared__ int sh_bin1, sh_above1, sh_bin2, sh_above2, sh_bin3, sh_above3;
    __shared__ int sh_out, sh_eqc;
    const int t = threadIdx.x;

    for (int i = t; i < LD; i += 1024) {
        unsigned int u = __float_as_uint(g_M[(size_t)bh * LD + i]);
        keys[i] = (u & 0x80000000u) ? ~u : (u | 0x80000000u);
    }
    for (int i = t; i < 4096; i += 1024) hist[i] = 0;
    __syncthreads();

    for (int i = t; i < LD; i += 1024) atomicAdd(&hist[keys[i] >> 20], 1);
    __syncthreads();
    if (t < 32) find_bin(hist, 4096, NTOP, &sh_bin1, &sh_above1, t);
    __syncthreads();
    const unsigned int b1 = (unsigned int)sh_bin1;
    const int above1 = sh_above1;
    __syncthreads();

    for (int i = t; i < 4096; i += 1024) hist[i] = 0;
    __syncthreads();
    for (int i = t; i < LD; i += 1024)
        if ((keys[i] >> 20) == b1) atomicAdd(&hist[(keys[i] >> 8) & 0xFFFu], 1);
    __syncthreads();
    if (t < 32) find_bin(hist, 4096, NTOP - above1, &sh_bin2, &sh_above2, t);
    __syncthreads();
    const unsigned int b2 = (unsigned int)sh_bin2;
    const unsigned int pref2 = (b1 << 12) | b2;
    const int above12 = above1 + sh_above2;
    __syncthreads();

    if (t < 256) hist[t] = 0;
    __syncthreads();
    for (int i = t; i < LD; i += 1024)
        if ((keys[i] >> 8) == pref2) atomicAdd(&hist[keys[i] & 0xFFu], 1);
    __syncthreads();
    if (t < 32) find_bin(hist, 256, NTOP - above12, &sh_bin3, &sh_above3, t);
    if (t == 0) { sh_out = 0; sh_eqc = 0; }
    __syncthreads();

    const unsigned int thr = (b1 << 20) | (b2 << 8) | (unsigned int)sh_bin3;

    for (int i = t; i < LD; i += 1024) {
        unsigned int k = keys[i];
        if (k > thr) {
            int p = atomicAdd(&sh_out, 1);
            g_top[bh * NTOP + p] = i;
        } else if (k == thr) {
            int c = atomicAdd(&sh_eqc, 1);
            if (c < 512) eqidx[c] = i;
        }
    }
    __syncthreads();

    if (t == 0) {
        const int a = sh_out;
        const int need = NTOP - a;
        int c = sh_eqc;
        if (c > 512) c = 512;
        for (int j = 0; j < need; j++) {
            int best = 1 << 30, bi = 0;
            for (int i2 = 0; i2 < c; i2++) {
                int v = eqidx[i2];
                if (v < best) { best = v; bi = i2; }
            }
            g_top[bh * NTOP + a + j] = best;
            eqidx[bi] = 1 << 30;
        }
    }
}

// ---------------- fused attention: P=exp(QK/8) in smem, sum + P@V ------------
__global__ __launch_bounds__(256) void fused_attn_kernel() {
    const int kc = blockIdx.x;
    const int h = blockIdx.y;
    const int b = blockIdx.z;
    const int bh = b * NH + h;
    const int t = threadIdx.x;
    const int row = t >> 2;
    const int q4 = t & 3;

    __shared__ float qs[NU][DH];
    __shared__ float Vs[64][DH];
    __shared__ float Ps[NU][64];

    for (int p = t; p < NU * 16; p += 256) {
        const int u = p >> 4;
        const int i = p & 15;
        const int l = g_top[bh * NTOP + u];
        ((float4*)qs[u])[i] =
            ((const float4*)(g_Q + ((size_t)b * LD + l) * DM + h * DH))[i];
    }

    float acc[3][4];
    float sp[3];
#pragma unroll
    for (int it = 0; it < 3; it++) {
        sp[it] = 0.0f;
#pragma unroll
        for (int c = 0; c < 4; c++) acc[it][c] = 0.0f;
    }
    __syncthreads();

    for (int sc = 0; sc < 8; sc++) {
        const int kbase = kc * 512 + sc * 64;

        for (int p = t; p < 64 * 16; p += 256) {
            const int kk = p >> 4;
            const int i = p & 15;
            ((float4*)Vs[kk])[i] =
                ((const float4*)(g_V + ((size_t)b * LE + kbase + kk) * DM + h * DH))[i];
        }

        const float4* kp =
            (const float4*)(g_K + ((size_t)b * LE + kbase + row) * DM + h * DH) + q4 * 4;
        float4 kr0 = kp[0], kr1 = kp[1], kr2 = kp[2], kr3 = kp[3];

#pragma unroll 5
        for (int u = 0; u < NU; u++) {
            const float4* qq = (const float4*)(qs[u]) + q4 * 4;
            float4 q0 = qq[0], q1 = qq[1], q2 = qq[2], q3 = qq[3];
            float s = kr0.x * q0.x + kr0.y * q0.y + kr0.z * q0.z + kr0.w * q0.w
                    + kr1.x * q1.x + kr1.y * q1.y + kr1.z * q1.z + kr1.w * q1.w
                    + kr2.x * q2.x + kr2.y * q2.y + kr2.z * q2.z + kr2.w * q2.w
                    + kr3.x * q3.x + kr3.y * q3.y + kr3.z * q3.z + kr3.w * q3.w;
            s += __shfl_xor_sync(0xffffffffu, s, 1);
            s += __shfl_xor_sync(0xffffffffu, s, 2);
            if (q4 == 0) Ps[u][row] = __expf(s * 0.125f);
        }
        __syncthreads();

#pragma unroll
        for (int it = 0; it < 3; it++) {
            const int p = t + it * 256;
            if (p < NU * 16) {
                const int u = p >> 4;
                const int d4 = p & 15;
                float a0 = acc[it][0], a1 = acc[it][1], a2 = acc[it][2], a3 = acc[it][3];
                float ss = 0.0f;
                for (int kk = 0; kk < 64; kk++) {
                    const float pw = Ps[u][kk];
                    float4 vv = ((float4*)Vs[kk])[d4];
                    a0 += pw * vv.x; a1 += pw * vv.y;
                    a2 += pw * vv.z; a3 += pw * vv.w;
                    ss += pw;
                }
                acc[it][0] = a0; acc[it][1] = a1; acc[it][2] = a2; acc[it][3] = a3;
                if (d4 == 0) sp[it] += ss;
            }
        }
        __syncthreads();
    }

#pragma unroll
    for (int it = 0; it < 3; it++) {
        const int p = t + it * 256;
        if (p < NU * 16) {
            const int u = p >> 4;
            const int d4 = p & 15;
            float* dst = g_upd + ((size_t)(bh * NTOP + u)) * DH + d4 * 4;
            atomicAdd(dst + 0, acc[it][0]);
            atomicAdd(dst + 1, acc[it][1]);
            atomicAdd(dst + 2, acc[it][2]);
            atomicAdd(dst + 3, acc[it][3]);
            if (d4 == 0) atomicAdd(&g_se[bh * NTOP + u], sp[it]);
        }
    }
}

// ---------------- base output row per batch: vmean @ Wo + bo ----------------
__global__ void baseout_kernel(const float* __restrict__ Wo, const float* __restrict__ bo) {
    const int b = blockIdx.x;
    const int lane = threadIdx.x & 31;
    const int w = threadIdx.x >> 5;
    const int col = blockIdx.y * 32 + lane;
    float s = 0.0f;
    const int k0 = w * 64;
#pragma unroll 8
    for (int k = k0; k < k0 + 64; k++)
        s += g_vmean[b * DM + k] * Wo[(size_t)k * DM + col];
    __shared__ float red[8][32];
    red[w][lane] = s;
    __syncthreads();
    if (w == 0) {
        float tot = bo[col];
#pragma unroll
        for (int j = 0; j < 8; j++) tot += red[j][lane];
        g_base[b * DM + col] = tot;
    }
}

// ---------------- fill output with base rows --------------------------------
__global__ void fill_kernel(float* __restrict__ out) {
    const size_t bl = blockIdx.x;
    const int b = blockIdx.x >> 12;
    float4 v = ((const float4*)(g_base + b * DM))[threadIdx.x];
    ((float4*)(out + bl * DM))[threadIdx.x] = v;
}

// ---------------- scatter corrections: (upd/se - vmean_h) @ Wo_h ------------
__global__ void scatter_kernel(const float* __restrict__ Wo, float* __restrict__ out) {
    const int u = blockIdx.x;
    const int h = blockIdx.y;
    const int b = blockIdx.z;
    const int bh = b * NH + h;
    __shared__ float delta[DH];
    __shared__ int lsh;
    __shared__ float inv_sh;
    const int t = threadIdx.x;

    if (t == 0) {
        lsh = g_top[bh * NTOP + u];
        inv_sh = 1.0f / g_se[bh * NTOP + u];
    }
    __syncthreads();
    if (t < DH)
        delta[t] = g_upd[((size_t)(bh * NTOP + u)) * DH + t] * inv_sh
                 - g_vmean[b * DM + h * DH + t];
    __syncthreads();

    const int l = lsh;
    float s = 0.0f;
#pragma unroll 8
    for (int d = 0; d < DH; d++) s += delta[d] * Wo[(size_t)(h * DH + d) * DM + t];
    atomicAdd(&out[((size_t)b * LD + l) * DM + t], s);
}

// ---------------- launch ----------------------------------------------------
extern "C" void kernel_launch(void* const* d_in, const int* in_sizes, int n_in,
                              void* d_out, int out_size) {
    const float* x       = (const float*)d_in[0];
    const float* context = (const float*)d_in[1];
    const float* Wq      = (const float*)d_in[2];
    const float* bq      = (const float*)d_in[3];
    const float* Wk      = (const float*)d_in[4];
    const float* bk      = (const float*)d_in[5];
    const float* Wv      = (const float*)d_in[6];
    const float* bv      = (const float*)d_in[7];
    const float* Wo      = (const float*)d_in[8];
    const float* bo      = (const float*)d_in[9];
    const int*   sidx    = (const int*)d_in[10];
    float* out = (float*)d_out;

    float *pQ, *pK, *pV;
    cudaGetSymbolAddress((void**)&pQ, g_Q);
    cudaGetSymbolAddress((void**)&pK, g_K);
    cudaGetSymbolAddress((void**)&pV, g_V);

    static int inited = 0;
    static cudaStream_t s1, s2;
    static cudaEvent_t ev0, evQ, evK, evV, evFill;
    if (!inited) {
        cudaFuncSetAttribute(tgemm512, cudaFuncAttributeMaxDynamicSharedMemorySize,
                             TG_SMEM_BYTES);
        cudaStreamCreateWithFlags(&s1, cudaStreamNonBlocking);
        cudaStreamCreateWithFlags(&s2, cudaStreamNonBlocking);
        cudaEventCreateWithFlags(&ev0, cudaEventDisableTiming);
        cudaEventCreateWithFlags(&evQ, cudaEventDisableTiming);
        cudaEventCreateWithFlags(&evK, cudaEventDisableTiming);
        cudaEventCreateWithFlags(&evV, cudaEventDisableTiming);
        cudaEventCreateWithFlags(&evFill, cudaEventDisableTiming);
        inited = 1;
    }

    // main: zero first (fused/scatter accumulate atomically into zeroed bufs)
    zero_kernel<<<360, 256>>>();
    cudaEventRecord(ev0, 0);

    // s1: Q-GEMM concurrent with K-GEMM on main
    cudaStreamWaitEvent(s1, ev0, 0);
    tgemm512<<<dim3(DM / 128, (NB * LD) / 128), 128, TG_SMEM_BYTES, s1>>>(x, Wq, bq, pQ);
    cudaEventRecord(evQ, s1);

    // main: K-GEMM
    tgemm512<<<dim3(DM / 128, (NB * LE) / 128), 128, TG_SMEM_BYTES>>>(context, Wk, bk, pK);
    cudaEventRecord(evK, 0);

    // s2: V branch starts after K-GEMM (overlaps sample_m)
    cudaStreamWaitEvent(s2, evK, 0);
    tgemm512<<<dim3(DM / 128, (NB * LE) / 128), 128, TG_SMEM_BYTES, s2>>>(context, Wv, bv, pV);
    cudaEventRecord(evV, s2);
    vmean_kernel<<<NB * 32, 512, 0, s2>>>();
    baseout_kernel<<<dim3(NB, 16), 256, 0, s2>>>(Wo, bo);
    fill_kernel<<<NB * LD, 128, 0, s2>>>(out);
    cudaEventRecord(evFill, s2);

    // main: sampling path (needs Q and K)
    cudaStreamWaitEvent(0, evQ, 0);
    sample_m_kernel<<<NB * LD, 256>>>(sidx);
    topk_kernel<<<NB * NH, 1024>>>();

    cudaStreamWaitEvent(0, evV, 0);       // fused needs V
    fused_attn_kernel<<<dim3(8, NH, NB), 256>>>();

    cudaStreamWaitEvent(0, evFill, 0);    // scatter writes over filled output
    scatter_kernel<<<dim3(NTOP, NH, NB), 512>>>(Wo, out);
}

// round 16
// speedup vs baseline: 1.4573x; 1.0245x over previous
#include <cuda_runtime.h>
#include <cuda_fp16.h>
#include <stdint.h>
#include <math.h>

#define NB 4
#define LD 4096
#define LE 4096
#define DM 512
#define NH 8
#define DH 64
#define NU 45
#define NTOP 45

// ---------------- scratch (static __device__, no allocation) ----------------
__device__ float g_Q[NB * LD * DM];
__device__ float g_K[NB * LE * DM];
__device__ __half g_Kh[NB * LE * DM];             // fp16 shadow of K for sampling
__device__ float g_V[NB * LE * DM];
__device__ float g_M[NB * NH * LD];
__device__ int   g_top[NB * NH * NTOP];
__device__ float g_se[NB * NH * NTOP];            // row sums of P (atomic)
__device__ float g_upd[NB * NH * NTOP * DH];      // unnormalized P@V (atomic)
__device__ float g_vmean[NB * DM];
__device__ float g_base[NB * DM];

// ---------------- zero scratch that is atomically accumulated ----------------
__global__ void zero_kernel() {
    int i = blockIdx.x * 256 + threadIdx.x;
    if (i < NB * DM) g_vmean[i] = 0.0f;
    if (i < NB * NH * NTOP * DH) g_upd[i] = 0.0f;
    if (i < NB * NH * NTOP) g_se[i] = 0.0f;
}

// ---------------- fp32 K -> fp16 shadow (streaming convert) -----------------
// grid 8192 x 256: each thread converts 4 floats -> 4 halves
__global__ void k2h_kernel() {
    size_t i = ((size_t)blockIdx.x * 256 + threadIdx.x) * 4;
    float4 v = *(const float4*)(g_K + i);
    __half2 h0 = __float22half2_rn(make_float2(v.x, v.y));
    __half2 h1 = __float22half2_rn(make_float2(v.z, v.w));
    uint2 packed = make_uint2(*(uint32_t*)&h0, *(uint32_t*)&h1);
    *(uint2*)(g_Kh + i) = packed;
}

// ---------------- helpers for tf32 tensor-core GEMM -------------------------
__device__ __forceinline__ uint32_t f2tf32(float v) {
    uint32_t u;
    asm volatile("cvt.rna.tf32.f32 %0, %1;" : "=r"(u) : "f"(v));
    return u;
}

__device__ __forceinline__ void cpasync16(void* smem_dst, const void* gsrc) {
    uint32_t d = (uint32_t)__cvta_generic_to_shared(smem_dst);
    asm volatile("cp.async.cg.shared.global [%0], [%1], 16;" :: "r"(d), "l"(gsrc));
}

#define CP_COMMIT() asm volatile("cp.async.commit_group;")
#define CP_WAIT(N)  asm volatile("cp.async.wait_group %0;" :: "n"(N))

#define AS_STRIDE 36
#define BS_STRIDE 136
#define AS_BUF (128 * AS_STRIDE)
#define BS_BUF (32 * BS_STRIDE)
#define TG_SMEM_BYTES ((2 * AS_BUF + 2 * BS_BUF) * 4)

// ---------------- tf32 tensor-core GEMM: C(Mx512)=A(Mx512)@W(512x512)+b -----
// block 128x128, BK=32, 128 threads = 4 warps (2x2), warp tile 64x64.
__global__ __launch_bounds__(128, 2) void tgemm512(const float* __restrict__ A,
                                                   const float* __restrict__ W,
                                                   const float* __restrict__ bias,
                                                   float* __restrict__ C) {
    extern __shared__ float sm[];
    float* As = sm;
    float* Bs = sm + 2 * AS_BUF;

    const int bm = blockIdx.y * 128;
    const int bn = blockIdx.x * 128;
    const int tid = threadIdx.x;
    const int lane = tid & 31;
    const int wid = tid >> 5;
    const int wm = (wid & 1) * 64;
    const int wn = (wid >> 1) * 64;
    const int g = lane >> 2;
    const int t4 = lane & 3;

    float acc[4][8][4];
#pragma unroll
    for (int mt = 0; mt < 4; mt++)
#pragma unroll
        for (int nt = 0; nt < 8; nt++)
#pragma unroll
            for (int c = 0; c < 4; c++) acc[mt][nt][c] = 0.0f;

    const float* Abase = A + (size_t)bm * DM;
    const float* Bbase = W + bn;

#define LOAD_TILE(kt, buf)                                                     \
    do {                                                                       \
        const float* Ag = Abase + (kt) * 32;                                   \
        const float* Bg = Bbase + (size_t)((kt) * 32) * DM;                    \
        _Pragma("unroll")                                                      \
        for (int i = 0; i < 8; i++) {                                          \
            int idx = tid + i * 128;                                           \
            int r = idx >> 3, c = (idx & 7) * 4;                               \
            cpasync16(&As[(buf) * AS_BUF + r * AS_STRIDE + c],                 \
                      Ag + (size_t)r * DM + c);                                \
        }                                                                      \
        _Pragma("unroll")                                                      \
        for (int i = 0; i < 8; i++) {                                          \
            int idx = tid + i * 128;                                           \
            int r = idx >> 5, c = (idx & 31) * 4;                              \
            cpasync16(&Bs[(buf) * BS_BUF + r * BS_STRIDE + c],                 \
                      Bg + (size_t)r * DM + c);                                \
        }                                                                      \
    } while (0)

    LOAD_TILE(0, 0);
    CP_COMMIT();

    for (int kt = 0; kt < 16; kt++) {
        const int buf = kt & 1;
        if (kt < 15) {
            LOAD_TILE(kt + 1, buf ^ 1);
            CP_COMMIT();
            CP_WAIT(1);
        } else {
            CP_WAIT(0);
        }
        __syncthreads();

        const float* Ab = As + buf * AS_BUF;
        const float* Bb = Bs + buf * BS_BUF;
#pragma unroll
        for (int k8 = 0; k8 < 4; k8++) {
            const int kk = k8 * 8;
            uint32_t af[4][4];
#pragma unroll
            for (int mt = 0; mt < 4; mt++) {
                const int rb = wm + mt * 16 + g;
                af[mt][0] = f2tf32(Ab[(rb)*AS_STRIDE + kk + t4]);
                af[mt][1] = f2tf32(Ab[(rb + 8) * AS_STRIDE + kk + t4]);
                af[mt][2] = f2tf32(Ab[(rb)*AS_STRIDE + kk + t4 + 4]);
                af[mt][3] = f2tf32(Ab[(rb + 8) * AS_STRIDE + kk + t4 + 4]);
            }
            uint32_t bf[8][2];
#pragma unroll
            for (int nt = 0; nt < 8; nt++) {
                const int nb = wn + nt * 8 + g;
                bf[nt][0] = f2tf32(Bb[(kk + t4) * BS_STRIDE + nb]);
                bf[nt][1] = f2tf32(Bb[(kk + t4 + 4) * BS_STRIDE + nb]);
            }
#pragma unroll
            for (int mt = 0; mt < 4; mt++)
#pragma unroll
                for (int nt = 0; nt < 8; nt++) {
                    asm volatile(
                        "mma.sync.aligned.m16n8k8.row.col.f32.tf32.tf32.f32 "
                        "{%0,%1,%2,%3}, {%4,%5,%6,%7}, {%8,%9}, {%0,%1,%2,%3};"
                        : "+f"(acc[mt][nt][0]), "+f"(acc[mt][nt][1]),
                          "+f"(acc[mt][nt][2]), "+f"(acc[mt][nt][3])
                        : "r"(af[mt][0]), "r"(af[mt][1]), "r"(af[mt][2]),
                          "r"(af[mt][3]), "r"(bf[nt][0]), "r"(bf[nt][1]));
                }
        }
        __syncthreads();
    }

    // ---- epilogue: bias add + store ----
#pragma unroll
    for (int mt = 0; mt < 4; mt++) {
        const int r0 = bm + wm + mt * 16 + g;
        const int r1 = r0 + 8;
#pragma unroll
        for (int nt = 0; nt < 8; nt++) {
            const int col = bn + wn + nt * 8 + 2 * t4;
            float2 bv = *(const float2*)&bias[col];
            float2 o0 = make_float2(acc[mt][nt][0] + bv.x, acc[mt][nt][1] + bv.y);
            float2 o1 = make_float2(acc[mt][nt][2] + bv.x, acc[mt][nt][3] + bv.y);
            *(float2*)&C[(size_t)r0 * DM + col] = o0;
            *(float2*)&C[(size_t)r1 * DM + col] = o1;
        }
    }
}

// ---------------- V column mean --------------------------------------------
__global__ void vmean_kernel() {
    const int b = blockIdx.x >> 5;
    const int slab = blockIdx.x & 31;
    const int t = threadIdx.x;
    const float* base = g_V + ((size_t)b * LE + slab * 128) * DM + t;
    float s = 0.0f;
    for (int r = 0; r < 128; r++) s += base[(size_t)r * DM];
    atomicAdd(&g_vmean[b * DM + t], s * (1.0f / (float)LE));
}

// ---------------- ProbSparse measure M: fp16-K warp-cooperative gather ------
__global__ __launch_bounds__(256) void sample_m_kernel(const int* __restrict__ sidx) {
    const int bl = blockIdx.x;
    const int b = bl >> 12;
    const int l = bl & (LD - 1);
    __shared__ float qs[DM];
    __shared__ int idx[NU];
    __shared__ float qk[NH][NU + 3];
    const int t = threadIdx.x;
    const int w = t >> 5;
    const int lane = t & 31;

    if (t < 128) ((float4*)qs)[t] = ((const float4*)(g_Q + (size_t)bl * DM))[t];
    if (t < NU) idx[t] = sidx[l * NU + t];
    __syncthreads();

    for (int u = w; u < NU; u += 8) {
        const uint2* kp = (const uint2*)(g_Kh + ((size_t)b * LE + idx[u]) * DM);
#pragma unroll
        for (int j = 0; j < 4; j++) {
            uint2 kv = kp[j * 32 + lane];                       // 4 halves
            float4 qv = ((const float4*)qs)[j * 32 + lane];     // matching 4 floats
            float2 a01 = __half22float2(*reinterpret_cast<const __half2*>(&kv.x));
            float2 a23 = __half22float2(*reinterpret_cast<const __half2*>(&kv.y));
            float s = a01.x * qv.x + a01.y * qv.y + a23.x * qv.z + a23.y * qv.w;
            s += __shfl_xor_sync(0xffffffffu, s, 1);
            s += __shfl_xor_sync(0xffffffffu, s, 2);
            s += __shfl_xor_sync(0xffffffffu, s, 4);
            s += __shfl_xor_sync(0xffffffffu, s, 8);
            if (lane == 0) qk[2 * j][u] = s;
            if (lane == 16) qk[2 * j + 1][u] = s;
        }
    }
    __syncthreads();

    if (t < NH) {
        float mx = -INFINITY, sm = 0.0f;
        for (int u = 0; u < NU; u++) {
            float v = qk[t][u];
            mx = fmaxf(mx, v);
            sm += v;
        }
        g_M[((size_t)(b * NH + t)) * LD + l] = mx - sm * (1.0f / (float)LE);
    }
}

// ---------------- find largest bin T with suffix-count >= target ------------
__device__ __forceinline__ void find_bin(const int* hist, int nbins, int target,
                                         int* sh_bin, int* sh_above, int lane) {
    int cum = 0;
    for (int base = nbins - 32; base >= 0; base -= 32) {
        int v = hist[base + lane];
        int tot = v;
#pragma unroll
        for (int o = 16; o > 0; o >>= 1) tot += __shfl_xor_sync(0xffffffffu, tot, o);
        if (cum + tot >= target) {
            if (lane == 0) {
                int c = cum;
                int b = base + 31;
                for (;; b--) {
                    int h = hist[b];
                    if (c + h >= target || b == base) break;
                    c += h;
                }
                *sh_bin = b;
                *sh_above = c;
            }
            return;
        }
        cum += tot;
    }
    if (lane == 0) { *sh_bin = 0; *sh_above = cum; }
}

// ---------------- exact top-k set via 3-pass radix select -------------------
__global__ __launch_bounds__(1024) void topk_kernel() {
    const int bh = blockIdx.x;
    __shared__ unsigned int keys[LD];
    __shared__ int hist[4096];
    __shared__ int eqidx[512];
    __shared__ int sh_bin1, sh_above1, sh_bin2, sh_above2, sh_bin3, sh_above3;
    __shared__ int sh_out, sh_eqc;
    const int t = threadIdx.x;

    for (int i = t; i < LD; i += 1024) {
        unsigned int u = __float_as_uint(g_M[(size_t)bh * LD + i]);
        keys[i] = (u & 0x80000000u) ? ~u : (u | 0x80000000u);
    }
    for (int i = t; i < 4096; i += 1024) hist[i] = 0;
    __syncthreads();

    for (int i = t; i < LD; i += 1024) atomicAdd(&hist[keys[i] >> 20], 1);
    __syncthreads();
    if (t < 32) find_bin(hist, 4096, NTOP, &sh_bin1, &sh_above1, t);
    __syncthreads();
    const unsigned int b1 = (unsigned int)sh_bin1;
    const int above1 = sh_above1;
    __syncthreads();

    for (int i = t; i < 4096; i += 1024) hist[i] = 0;
    __syncthreads();
    for (int i = t; i < LD; i += 1024)
        if ((keys[i] >> 20) == b1) atomicAdd(&hist[(keys[i] >> 8) & 0xFFFu], 1);
    __syncthreads();
    if (t < 32) find_bin(hist, 4096, NTOP - above1, &sh_bin2, &sh_above2, t);
    __syncthreads();
    const unsigned int b2 = (unsigned int)sh_bin2;
    const unsigned int pref2 = (b1 << 12) | b2;
    const int above12 = above1 + sh_above2;
    __syncthreads();

    if (t < 256) hist[t] = 0;
    __syncthreads();
    for (int i = t; i < LD; i += 1024)
        if ((keys[i] >> 8) == pref2) atomicAdd(&hist[keys[i] & 0xFFu], 1);
    __syncthreads();
    if (t < 32) find_bin(hist, 256, NTOP - above12, &sh_bin3, &sh_above3, t);
    if (t == 0) { sh_out = 0; sh_eqc = 0; }
    __syncthreads();

    const unsigned int thr = (b1 << 20) | (b2 << 8) | (unsigned int)sh_bin3;

    for (int i = t; i < LD; i += 1024) {
        unsigned int k = keys[i];
        if (k > thr) {
            int p = atomicAdd(&sh_out, 1);
            g_top[bh * NTOP + p] = i;
        } else if (k == thr) {
            int c = atomicAdd(&sh_eqc, 1);
            if (c < 512) eqidx[c] = i;
        }
    }
    __syncthreads();

    if (t == 0) {
        const int a = sh_out;
        const int need = NTOP - a;
        int c = sh_eqc;
        if (c > 512) c = 512;
        for (int j = 0; j < need; j++) {
            int best = 1 << 30, bi = 0;
            for (int i2 = 0; i2 < c; i2++) {
                int v = eqidx[i2];
                if (v < best) { best = v; bi = i2; }
            }
            g_top[bh * NTOP + a + j] = best;
            eqidx[bi] = 1 << 30;
        }
    }
}

// ---------------- fused attention: P=exp(QK/8) in smem, sum + P@V ------------
__global__ __launch_bounds__(256) void fused_attn_kernel() {
    const int kc = blockIdx.x;
    const int h = blockIdx.y;
    const int b = blockIdx.z;
    const int bh = b * NH + h;
    const int t = threadIdx.x;
    const int row = t >> 2;
    const int q4 = t & 3;

    __shared__ float qs[NU][DH];
    __shared__ float Vs[64][DH];
    __shared__ float Ps[NU][64];

    for (int p = t; p < NU * 16; p += 256) {
        const int u = p >> 4;
        const int i = p & 15;
        const int l = g_top[bh * NTOP + u];
        ((float4*)qs[u])[i] =
            ((const float4*)(g_Q + ((size_t)b * LD + l) * DM + h * DH))[i];
    }

    float acc[3][4];
    float sp[3];
#pragma unroll
    for (int it = 0; it < 3; it++) {
        sp[it] = 0.0f;
#pragma unroll
        for (int c = 0; c < 4; c++) acc[it][c] = 0.0f;
    }
    __syncthreads();

    for (int sc = 0; sc < 8; sc++) {
        const int kbase = kc * 512 + sc * 64;

        for (int p = t; p < 64 * 16; p += 256) {
            const int kk = p >> 4;
            const int i = p & 15;
            ((float4*)Vs[kk])[i] =
                ((const float4*)(g_V + ((size_t)b * LE + kbase + kk) * DM + h * DH))[i];
        }

        const float4* kp =
            (const float4*)(g_K + ((size_t)b * LE + kbase + row) * DM + h * DH) + q4 * 4;
        float4 kr0 = kp[0], kr1 = kp[1], kr2 = kp[2], kr3 = kp[3];

#pragma unroll 5
        for (int u = 0; u < NU; u++) {
            const float4* qq = (const float4*)(qs[u]) + q4 * 4;
            float4 q0 = qq[0], q1 = qq[1], q2 = qq[2], q3 = qq[3];
            float s = kr0.x * q0.x + kr0.y * q0.y + kr0.z * q0.z + kr0.w * q0.w
                    + kr1.x * q1.x + kr1.y * q1.y + kr1.z * q1.z + kr1.w * q1.w
                    + kr2.x * q2.x + kr2.y * q2.y + kr2.z * q2.z + kr2.w * q2.w
                    + kr3.x * q3.x + kr3.y * q3.y + kr3.z * q3.z + kr3.w * q3.w;
            s += __shfl_xor_sync(0xffffffffu, s, 1);
            s += __shfl_xor_sync(0xffffffffu, s, 2);
            if (q4 == 0) Ps[u][row] = __expf(s * 0.125f);
        }
        __syncthreads();

#pragma unroll
        for (int it = 0; it < 3; it++) {
            const int p = t + it * 256;
            if (p < NU * 16) {
                const int u = p >> 4;
                const int d4 = p & 15;
                float a0 = acc[it][0], a1 = acc[it][1], a2 = acc[it][2], a3 = acc[it][3];
                float ss = 0.0f;
                for (int kk = 0; kk < 64; kk++) {
                    const float pw = Ps[u][kk];
                    float4 vv = ((float4*)Vs[kk])[d4];
                    a0 += pw * vv.x; a1 += pw * vv.y;
                    a2 += pw * vv.z; a3 += pw * vv.w;
                    ss += pw;
                }
                acc[it][0] = a0; acc[it][1] = a1; acc[it][2] = a2; acc[it][3] = a3;
                if (d4 == 0) sp[it] += ss;
            }
        }
        __syncthreads();
    }

#pragma unroll
    for (int it = 0; it < 3; it++) {
        const int p = t + it * 256;
        if (p < NU * 16) {
            const int u = p >> 4;
            const int d4 = p & 15;
            float* dst = g_upd + ((size_t)(bh * NTOP + u)) * DH + d4 * 4;
            atomicAdd(dst + 0, acc[it][0]);
            atomicAdd(dst + 1, acc[it][1]);
            atomicAdd(dst + 2, acc[it][2]);
            atomicAdd(dst + 3, acc[it][3]);
            if (d4 == 0) atomicAdd(&g_se[bh * NTOP + u], sp[it]);
        }
    }
}

// ---------------- base output row per batch: vmean @ Wo + bo ----------------
__global__ void baseout_kernel(const float* __restrict__ Wo, const float* __restrict__ bo) {
    const int b = blockIdx.x;
    const int lane = threadIdx.x & 31;
    const int w = threadIdx.x >> 5;
    const int col = blockIdx.y * 32 + lane;
    float s = 0.0f;
    const int k0 = w * 64;
#pragma unroll 8
    for (int k = k0; k < k0 + 64; k++)
        s += g_vmean[b * DM + k] * Wo[(size_t)k * DM + col];
    __shared__ float red[8][32];
    red[w][lane] = s;
    __syncthreads();
    if (w == 0) {
        float tot = bo[col];
#pragma unroll
        for (int j = 0; j < 8; j++) tot += red[j][lane];
        g_base[b * DM + col] = tot;
    }
}

// ---------------- fill output with base rows --------------------------------
__global__ void fill_kernel(float* __restrict__ out) {
    const size_t bl = blockIdx.x;
    const int b = blockIdx.x >> 12;
    float4 v = ((const float4*)(g_base + b * DM))[threadIdx.x];
    ((float4*)(out + bl * DM))[threadIdx.x] = v;
}

// ---------------- scatter corrections: (upd/se - vmean_h) @ Wo_h ------------
__global__ void scatter_kernel(const float* __restrict__ Wo, float* __restrict__ out) {
    const int u = blockIdx.x;
    const int h = blockIdx.y;
    const int b = blockIdx.z;
    const int bh = b * NH + h;
    __shared__ float delta[DH];
    __shared__ int lsh;
    __shared__ float inv_sh;
    const int t = threadIdx.x;

    if (t == 0) {
        lsh = g_top[bh * NTOP + u];
        inv_sh = 1.0f / g_se[bh * NTOP + u];
    }
    __syncthreads();
    if (t < DH)
        delta[t] = g_upd[((size_t)(bh * NTOP + u)) * DH + t] * inv_sh
                 - g_vmean[b * DM + h * DH + t];
    __syncthreads();

    const int l = lsh;
    float s = 0.0f;
#pragma unroll 8
    for (int d = 0; d < DH; d++) s += delta[d] * Wo[(size_t)(h * DH + d) * DM + t];
    atomicAdd(&out[((size_t)b * LD + l) * DM + t], s);
}

// ---------------- launch ----------------------------------------------------
extern "C" void kernel_launch(void* const* d_in, const int* in_sizes, int n_in,
                              void* d_out, int out_size) {
    const float* x       = (const float*)d_in[0];
    const float* context = (const float*)d_in[1];
    const float* Wq      = (const float*)d_in[2];
    const float* bq      = (const float*)d_in[3];
    const float* Wk      = (const float*)d_in[4];
    const float* bk      = (const float*)d_in[5];
    const float* Wv      = (const float*)d_in[6];
    const float* bv      = (const float*)d_in[7];
    const float* Wo      = (const float*)d_in[8];
    const float* bo      = (const float*)d_in[9];
    const int*   sidx    = (const int*)d_in[10];
    float* out = (float*)d_out;

    float *pQ, *pK, *pV;
    cudaGetSymbolAddress((void**)&pQ, g_Q);
    cudaGetSymbolAddress((void**)&pK, g_K);
    cudaGetSymbolAddress((void**)&pV, g_V);

    static int inited = 0;
    static cudaStream_t s1, s2;
    static cudaEvent_t ev0, evQ, evK, evV, evFill;
    if (!inited) {
        cudaFuncSetAttribute(tgemm512, cudaFuncAttributeMaxDynamicSharedMemorySize,
                             TG_SMEM_BYTES);
        cudaStreamCreateWithFlags(&s1, cudaStreamNonBlocking);
        cudaStreamCreateWithFlags(&s2, cudaStreamNonBlocking);
        cudaEventCreateWithFlags(&ev0, cudaEventDisableTiming);
        cudaEventCreateWithFlags(&evQ, cudaEventDisableTiming);
        cudaEventCreateWithFlags(&evK, cudaEventDisableTiming);
        cudaEventCreateWithFlags(&evV, cudaEventDisableTiming);
        cudaEventCreateWithFlags(&evFill, cudaEventDisableTiming);
        inited = 1;
    }

    // main: zero first (fused/scatter accumulate atomically into zeroed bufs)
    zero_kernel<<<360, 256>>>();
    cudaEventRecord(ev0, 0);

    // s1: Q-GEMM concurrent with K-GEMM on main
    cudaStreamWaitEvent(s1, ev0, 0);
    tgemm512<<<dim3(DM / 128, (NB * LD) / 128), 128, TG_SMEM_BYTES, s1>>>(x, Wq, bq, pQ);
    cudaEventRecord(evQ, s1);

    // main: K-GEMM, then fp16 shadow convert
    tgemm512<<<dim3(DM / 128, (NB * LE) / 128), 128, TG_SMEM_BYTES>>>(context, Wk, bk, pK);
    k2h_kernel<<<(NB * LE * DM) / (256 * 4), 256>>>();
    cudaEventRecord(evK, 0);

    // s2: V branch starts after K-GEMM (overlaps sample_m)
    cudaStreamWaitEvent(s2, evK, 0);
    tgemm512<<<dim3(DM / 128, (NB * LE) / 128), 128, TG_SMEM_BYTES, s2>>>(context, Wv, bv, pV);
    cudaEventRecord(evV, s2);
    vmean_kernel<<<NB * 32, 512, 0, s2>>>();
    baseout_kernel<<<dim3(NB, 16), 256, 0, s2>>>(Wo, bo);
    fill_kernel<<<NB * LD, 128, 0, s2>>>(out);
    cudaEventRecord(evFill, s2);

    // main: sampling path (needs Q and K shadow)
    cudaStreamWaitEvent(0, evQ, 0);
    sample_m_kernel<<<NB * LD, 256>>>(sidx);
    topk_kernel<<<NB * NH, 1024>>>();

    cudaStreamWaitEvent(0, evV, 0);       // fused needs V
    fused_attn_kernel<<<dim3(8, NH, NB), 256>>>();

    cudaStreamWaitEvent(0, evFill, 0);    // scatter writes over filled output
    scatter_kernel<<<dim3(NTOP, NH, NB), 512>>>(Wo, out);
}